// round 1
// baseline (speedup 1.0000x reference)
#include <cuda_runtime.h>
#include <math.h>

#define B_   2
#define N_   1024
#define D_   768
#define H_   16
#define HD_  48
#define HID_ 1536
#define M_   (B_*N_)      // 2048
#define EPS_ 1e-5f

// ---------------- scratch (static device buffers; no allocation) ----------------
__device__ float g_an  [M_*D_];
__device__ float g_sn  [M_*D_];
__device__ float g_c1  [M_*D_];
__device__ float g_c2  [M_*D_];
__device__ float g_bm  [M_*D_];
__device__ float g_q   [M_*D_];
__device__ float g_k   [M_*D_];
__device__ float g_v   [M_*D_];
__device__ float g_gt  [M_*D_];
__device__ float g_o   [M_*D_];
__device__ float g_og  [M_*D_];
__device__ float g_xw  [M_*D_];
__device__ float g_sig [M_*D_];
__device__ float g_anew[M_*D_];
__device__ float g_hb  [M_*D_];
__device__ float g_sw  [M_*2*HID_];
__device__ float g_ab  [M_*HID_];
__device__ float g_hid [M_*HID_];
__device__ float g_p   [(size_t)H_*B_*N_*N_];   // 128 MB attention matrix

// ---------------- block reductions (256 threads) ----------------
__device__ __forceinline__ float block_reduce_sum(float v) {
    __shared__ float sh[8];
    __shared__ float res;
    __syncthreads();
    #pragma unroll
    for (int o = 16; o > 0; o >>= 1) v += __shfl_down_sync(0xffffffffu, v, o);
    int lane = threadIdx.x & 31, w = threadIdx.x >> 5;
    if (lane == 0) sh[w] = v;
    __syncthreads();
    if (w == 0) {
        v = (lane < 8) ? sh[lane] : 0.f;
        #pragma unroll
        for (int o = 4; o > 0; o >>= 1) v += __shfl_down_sync(0xffffffffu, v, o);
        if (lane == 0) res = v;
    }
    __syncthreads();
    return res;
}

__device__ __forceinline__ float block_reduce_max(float v) {
    __shared__ float sh[8];
    __shared__ float res;
    __syncthreads();
    #pragma unroll
    for (int o = 16; o > 0; o >>= 1) v = fmaxf(v, __shfl_down_sync(0xffffffffu, v, o));
    int lane = threadIdx.x & 31, w = threadIdx.x >> 5;
    if (lane == 0) sh[w] = v;
    __syncthreads();
    if (w == 0) {
        v = (lane < 8) ? sh[lane] : -1e30f;
        #pragma unroll
        for (int o = 4; o > 0; o >>= 1) v = fmaxf(v, __shfl_down_sync(0xffffffffu, v, o));
        if (lane == 0) res = v;
    }
    __syncthreads();
    return res;
}

// ---------------- LayerNorm (one block per row, 256 thr, D=768=3*256) ----------------
__global__ __launch_bounds__(256) void ln_kernel(const float* __restrict__ x,
                                                 const float* __restrict__ w,
                                                 float* __restrict__ out) {
    int row = blockIdx.x;
    const float* xr = x + (size_t)row * D_;
    float* orow = out + (size_t)row * D_;
    float lv[3];
    float s = 0.f;
    #pragma unroll
    for (int i = 0; i < 3; i++) { lv[i] = xr[threadIdx.x + i*256]; s += lv[i]; }
    float mean = block_reduce_sum(s) * (1.f / D_);
    float vs = 0.f;
    #pragma unroll
    for (int i = 0; i < 3; i++) { float d = lv[i] - mean; vs += d * d; }
    float var = block_reduce_sum(vs) * (1.f / D_);
    float rstd = rsqrtf(var + EPS_);
    #pragma unroll
    for (int i = 0; i < 3; i++) {
        int c = threadIdx.x + i*256;
        float y = (lv[i] - mean) * rstd;
        if (w) y *= w[c];
        orow[c] = y;
    }
}

// ---------------- generic SGEMM: C[M,N] = A[M,K] @ W[K,N] (+bias) (+sigmoid) ----------
// 64x64 tile, BK=16, 256 threads, 4x4 per thread. M%64==0, N%64==0, K%16==0.
__global__ __launch_bounds__(256) void sgemm_kernel(const float* __restrict__ A,
                                                    const float* __restrict__ W,
                                                    const float* __restrict__ bias,
                                                    float* __restrict__ C,
                                                    int Ndim, int Kdim, int act) {
    __shared__ float As[16][64];
    __shared__ float Ws[16][64];
    const int bm = blockIdx.y * 64, bn = blockIdx.x * 64;
    const int tid = threadIdx.x;
    const int tx = tid & 15, ty = tid >> 4;
    float acc[4][4] = {};
    for (int k0 = 0; k0 < Kdim; k0 += 16) {
        #pragma unroll
        for (int l = 0; l < 4; l++) {
            int idx = tid + l * 256;
            int r = idx >> 4, c = idx & 15;
            As[c][r] = A[(size_t)(bm + r) * Kdim + k0 + c];
        }
        #pragma unroll
        for (int l = 0; l < 4; l++) {
            int idx = tid + l * 256;
            int r = idx >> 6, c = idx & 63;
            Ws[r][c] = W[(size_t)(k0 + r) * Ndim + bn + c];
        }
        __syncthreads();
        #pragma unroll
        for (int kk = 0; kk < 16; kk++) {
            float av[4], wv[4];
            #pragma unroll
            for (int i = 0; i < 4; i++) av[i] = As[kk][ty * 4 + i];
            #pragma unroll
            for (int j = 0; j < 4; j++) wv[j] = Ws[kk][tx * 4 + j];
            #pragma unroll
            for (int i = 0; i < 4; i++)
                #pragma unroll
                for (int j = 0; j < 4; j++)
                    acc[i][j] = fmaf(av[i], wv[j], acc[i][j]);
        }
        __syncthreads();
    }
    #pragma unroll
    for (int i = 0; i < 4; i++) {
        size_t r = bm + ty * 4 + i;
        #pragma unroll
        for (int j = 0; j < 4; j++) {
            int c = bn + tx * 4 + j;
            float vv = acc[i][j];
            if (bias) vv += bias[c];
            if (act == 1) vv = 1.f / (1.f + expf(-vv));
            C[r * (size_t)Ndim + c] = vv;
        }
    }
}

// ---------------- attention scores: p[hb,q,k] = (q . k)*scale + z ----------------
__global__ __launch_bounds__(256) void scores_kernel(const float* __restrict__ q,
                                                     const float* __restrict__ k,
                                                     const float* __restrict__ z,
                                                     float* __restrict__ p) {
    __shared__ float Qs[64][49];
    __shared__ float Ks[64][49];
    const int batch = blockIdx.z;             // batch = h*B + b
    const int h = batch / B_, b = batch % B_;
    const int qi0 = blockIdx.y * 64, ki0 = blockIdx.x * 64;
    const size_t qbase = ((size_t)(b * N_) + qi0) * D_ + h * HD_;
    const size_t kbase = ((size_t)(b * N_) + ki0) * D_ + h * HD_;
    const int tid = threadIdx.x, tx = tid & 15, ty = tid >> 4;
    for (int l = tid; l < 64 * 48; l += 256) {
        int r = l / 48, c = l % 48;
        Qs[r][c] = q[qbase + (size_t)r * D_ + c];
        Ks[r][c] = k[kbase + (size_t)r * D_ + c];
    }
    __syncthreads();
    float acc[4][4] = {};
    #pragma unroll 8
    for (int kk = 0; kk < 48; kk++) {
        float av[4], wv[4];
        #pragma unroll
        for (int i = 0; i < 4; i++) av[i] = Qs[ty * 4 + i][kk];
        #pragma unroll
        for (int j = 0; j < 4; j++) wv[j] = Ks[tx * 4 + j][kk];
        #pragma unroll
        for (int i = 0; i < 4; i++)
            #pragma unroll
            for (int j = 0; j < 4; j++)
                acc[i][j] = fmaf(av[i], wv[j], acc[i][j]);
    }
    const float scale = 0.14433756729740643f;   // 1/sqrt(48)
    const size_t pbase = ((size_t)batch * N_ + qi0) * N_ + ki0;
    #pragma unroll
    for (int i = 0; i < 4; i++)
        #pragma unroll
        for (int j = 0; j < 4; j++) {
            size_t off = pbase + (size_t)(ty * 4 + i) * N_ + tx * 4 + j;
            p[off] = acc[i][j] * scale + z[off];
        }
}

// ---------------- row softmax over last dim (N=1024), one block per row ------------
__global__ __launch_bounds__(256) void softmax_kernel(float* __restrict__ p) {
    const size_t row = blockIdx.x;
    float* pr = p + row * (size_t)N_;
    float lv[4];
    float mx = -1e30f;
    #pragma unroll
    for (int i = 0; i < 4; i++) { lv[i] = pr[threadIdx.x + i*256]; mx = fmaxf(mx, lv[i]); }
    mx = block_reduce_max(mx);
    float s = 0.f;
    #pragma unroll
    for (int i = 0; i < 4; i++) { lv[i] = expf(lv[i] - mx); s += lv[i]; }
    s = block_reduce_sum(s);
    float inv = 1.f / s;
    #pragma unroll
    for (int i = 0; i < 4; i++) pr[threadIdx.x + i*256] = lv[i] * inv;
}

// ---------------- o[b,q,h,:] = sum_k p[hb,q,k] * v[b,k,h,:] ----------------
__global__ __launch_bounds__(256) void attn_o_kernel(const float* __restrict__ p,
                                                     const float* __restrict__ v,
                                                     float* __restrict__ o) {
    __shared__ float Ps[16][64];
    __shared__ float Vs[16][48];
    const int batch = blockIdx.z;
    const int h = batch / B_, b = batch % B_;
    const int qi0 = blockIdx.y * 64;
    const int tid = threadIdx.x, tx = tid & 15, ty = tid >> 4;
    float acc[4][3] = {};
    const size_t pbase = ((size_t)batch * N_ + qi0) * N_;
    const size_t vbase = ((size_t)(b * N_)) * D_ + h * HD_;
    for (int k0 = 0; k0 < N_; k0 += 16) {
        for (int l = tid; l < 64 * 16; l += 256) {
            int r = l >> 4, c = l & 15;
            Ps[c][r] = p[pbase + (size_t)r * N_ + k0 + c];
        }
        for (int l = tid; l < 16 * 48; l += 256) {
            int r = l / 48, c = l % 48;
            Vs[r][c] = v[vbase + (size_t)(k0 + r) * D_ + c];
        }
        __syncthreads();
        #pragma unroll
        for (int kk = 0; kk < 16; kk++) {
            float av[4], wv[3];
            #pragma unroll
            for (int i = 0; i < 4; i++) av[i] = Ps[kk][ty * 4 + i];
            #pragma unroll
            for (int j = 0; j < 3; j++) wv[j] = Vs[kk][tx * 3 + j];
            #pragma unroll
            for (int i = 0; i < 4; i++)
                #pragma unroll
                for (int j = 0; j < 3; j++)
                    acc[i][j] = fmaf(av[i], wv[j], acc[i][j]);
        }
        __syncthreads();
    }
    #pragma unroll
    for (int i = 0; i < 4; i++)
        #pragma unroll
        for (int j = 0; j < 3; j++)
            o[((size_t)(b * N_) + qi0 + ty * 4 + i) * D_ + h * HD_ + tx * 3 + j] = acc[i][j];
}

// ---------------- elementwise fusions ----------------
__global__ void ew_adaln_kernel(const float* __restrict__ an, const float* __restrict__ sig,
                                const float* __restrict__ c2, float* __restrict__ out, int n) {
    int i = blockIdx.x * blockDim.x + threadIdx.x;
    if (i < n) out[i] = an[i] * sig[i] + c2[i];
}
__global__ void ew_mul_kernel(const float* __restrict__ a, const float* __restrict__ b,
                              float* __restrict__ out, int n) {
    int i = blockIdx.x * blockDim.x + threadIdx.x;
    if (i < n) out[i] = a[i] * b[i];
}
__global__ void ew_gate_add_kernel(const float* __restrict__ base, const float* __restrict__ g,
                                   const float* __restrict__ x, float* __restrict__ out, int n) {
    int i = blockIdx.x * blockDim.x + threadIdx.x;
    if (i < n) out[i] = base[i] + g[i] * x[i];
}
__global__ void ew_swiglu_kernel(const float* __restrict__ sw, const float* __restrict__ ab,
                                 float* __restrict__ out, int n) {
    int i = blockIdx.x * blockDim.x + threadIdx.x;
    if (i < n) {
        int row = i / HID_, j = i - row * HID_;
        float u  = sw[(size_t)row * (2 * HID_) + j];
        float gt = sw[(size_t)row * (2 * HID_) + HID_ + j];
        float sg = 1.f / (1.f + expf(-gt));
        out[i] = gt * sg * u * ab[i];
    }
}

// ---------------- host orchestration ----------------
static float* sym(const void* s) { void* p = nullptr; cudaGetSymbolAddress(&p, s); return (float*)p; }

extern "C" void kernel_launch(void* const* d_in, const int* in_sizes, int n_in,
                              void* d_out, int out_size) {
    const float* a          = (const float*)d_in[0];
    const float* s          = (const float*)d_in[1];
    const float* z          = (const float*)d_in[2];
    const float* ad1_snw    = (const float*)d_in[3];
    const float* ad1_ssw    = (const float*)d_in[4];
    const float* ad1_ssb    = (const float*)d_in[5];
    const float* ad1_sbw    = (const float*)d_in[6];
    const float* q_w        = (const float*)d_in[7];
    const float* q_b        = (const float*)d_in[8];
    const float* k_w        = (const float*)d_in[9];
    const float* v_w        = (const float*)d_in[10];
    const float* g_w        = (const float*)d_in[11];
    const float* o_w        = (const float*)d_in[12];
    const float* outproj_w  = (const float*)d_in[13];
    const float* outproj_b  = (const float*)d_in[14];
    const float* ad2_snw    = (const float*)d_in[15];
    const float* ad2_ssw    = (const float*)d_in[16];
    const float* ad2_ssb    = (const float*)d_in[17];
    const float* ad2_sbw    = (const float*)d_in[18];
    const float* swish_w    = (const float*)d_in[19];
    const float* a2b_w      = (const float*)d_in[20];
    const float* b2a_w      = (const float*)d_in[21];
    const float* op_w       = (const float*)d_in[22];
    const float* op_b       = (const float*)d_in[23];
    float* out = (float*)d_out;

    float *an = sym(g_an), *sn = sym(g_sn), *c1 = sym(g_c1), *c2 = sym(g_c2);
    float *bm = sym(g_bm), *qb = sym(g_q), *kb = sym(g_k), *vb = sym(g_v);
    float *gt = sym(g_gt), *ob = sym(g_o), *og = sym(g_og), *xw = sym(g_xw);
    float *sg = sym(g_sig), *anew = sym(g_anew), *hb = sym(g_hb);
    float *sw = sym(g_sw), *ab = sym(g_ab), *hid = sym(g_hid), *p = sym(g_p);

    const int nMD  = M_ * D_;
    const int nMH  = M_ * HID_;
    const dim3 gemmD(D_ / 64, M_ / 64);        // N=768
    const dim3 gemmH2(2 * HID_ / 64, M_ / 64); // N=3072
    const dim3 gemmH(HID_ / 64, M_ / 64);      // N=1536
    const int EW = 256;

    // ===== adaLN 1 =====
    ln_kernel<<<M_, 256>>>(a, nullptr, an);
    ln_kernel<<<M_, 256>>>(s, ad1_snw, sn);
    sgemm_kernel<<<gemmD, 256>>>(sn, ad1_ssw, ad1_ssb, c1, D_, D_, 1);  // sigmoid(sn@ssw+ssb)
    sgemm_kernel<<<gemmD, 256>>>(sn, ad1_sbw, nullptr, c2, D_, D_, 0);  // sn@sbw
    ew_adaln_kernel<<<nMD / EW, EW>>>(an, c1, c2, bm, nMD);             // b

    // ===== QKVG projections =====
    sgemm_kernel<<<gemmD, 256>>>(bm, q_w, q_b,     qb, D_, D_, 0);
    sgemm_kernel<<<gemmD, 256>>>(bm, k_w, nullptr, kb, D_, D_, 0);
    sgemm_kernel<<<gemmD, 256>>>(bm, v_w, nullptr, vb, D_, D_, 0);
    sgemm_kernel<<<gemmD, 256>>>(bm, g_w, nullptr, gt, D_, D_, 1);      // sigmoid gate

    // ===== attention =====
    scores_kernel<<<dim3(N_/64, N_/64, H_*B_), 256>>>(qb, kb, z, p);
    softmax_kernel<<<H_*B_*N_, 256>>>(p);
    attn_o_kernel<<<dim3(1, N_/64, H_*B_), 256>>>(p, vb, ob);

    // ===== output projection + gated residual =====
    ew_mul_kernel<<<nMD / EW, EW>>>(ob, gt, og, nMD);                   // o * g
    sgemm_kernel<<<gemmD, 256>>>(og, o_w, nullptr, xw, D_, D_, 0);      // x
    sgemm_kernel<<<gemmD, 256>>>(s, outproj_w, outproj_b, sg, D_, D_, 1);
    ew_gate_add_kernel<<<nMD / EW, EW>>>(a, sg, xw, anew, nMD);         // a = a + sig*x

    // ===== adaLN 2 =====
    ln_kernel<<<M_, 256>>>(anew, nullptr, an);
    ln_kernel<<<M_, 256>>>(s, ad2_snw, sn);
    sgemm_kernel<<<gemmD, 256>>>(sn, ad2_ssw, ad2_ssb, c1, D_, D_, 1);
    sgemm_kernel<<<gemmD, 256>>>(sn, ad2_sbw, nullptr, c2, D_, D_, 0);
    ew_adaln_kernel<<<nMD / EW, EW>>>(an, c1, c2, bm, nMD);             // a2

    // ===== MLP =====
    sgemm_kernel<<<gemmH2, 256>>>(bm, swish_w, nullptr, sw, 2*HID_, D_, 0);  // 2048x3072
    sgemm_kernel<<<gemmH,  256>>>(bm, a2b_w,   nullptr, ab, HID_, D_, 0);    // 2048x1536
    ew_swiglu_kernel<<<nMH / EW, EW>>>(sw, ab, hid, nMH);
    sgemm_kernel<<<gemmD, 256>>>(hid, b2a_w, nullptr, hb, D_, HID_, 0);      // K=1536
    sgemm_kernel<<<gemmD, 256>>>(s, op_w, op_b, sg, D_, D_, 1);
    ew_gate_add_kernel<<<nMD / EW, EW>>>(anew, sg, hb, out, nMD);            // a + t
}

// round 3
// speedup vs baseline: 2.4506x; 2.4506x over previous
#include <cuda_runtime.h>
#include <math.h>
#include <stdint.h>

#define B_   2
#define N_   1024
#define D_   768
#define H_   16
#define HD_  48
#define HID_ 1536
#define M_   (B_*N_)      // 2048
#define EPS_ 1e-5f

// ---------------- scratch (static device buffers; no allocation) ----------------
__device__ float g_an  [M_*D_];
__device__ float g_sn  [M_*D_];
__device__ float g_c1  [M_*D_];
__device__ float g_c2  [M_*D_];
__device__ float g_bm  [M_*D_];
__device__ float g_q   [M_*D_];
__device__ float g_k   [M_*D_];
__device__ float g_v   [M_*D_];
__device__ float g_gt  [M_*D_];
__device__ float g_o   [M_*D_];
__device__ float g_og  [M_*D_];
__device__ float g_xw  [M_*D_];
__device__ float g_sig [M_*D_];
__device__ float g_anew[M_*D_];
__device__ float g_hb  [M_*D_];
__device__ float g_sw  [M_*2*HID_];
__device__ float g_ab  [M_*HID_];
__device__ float g_hid [M_*HID_];
__device__ float g_p   [(size_t)H_*B_*N_*N_];   // 128 MB attention matrix

// =================================================================================
// tf32 mma.sync GEMM (base PTX ISA — works on compute_103 without the 'a' features)
// C[M,N] = A[M,K] @ W[K,N]  (+bias) (+sigmoid)
// 128x128x32 block tile, 256 thr, 8 warps (2x4), warp tile 64x32, m16n8k8 tf32.
// =================================================================================
__device__ __forceinline__ uint32_t f2tf32(float f) {
    uint32_t u;
    asm("cvt.rna.tf32.f32 %0, %1;" : "=r"(u) : "f"(f));
    return u;
}
__device__ __forceinline__ void mma_m16n8k8(float* c, const uint32_t* a, const uint32_t* b) {
    asm volatile(
        "mma.sync.aligned.m16n8k8.row.col.f32.tf32.tf32.f32 "
        "{%0,%1,%2,%3}, {%4,%5,%6,%7}, {%8,%9}, {%0,%1,%2,%3};"
        : "+f"(c[0]), "+f"(c[1]), "+f"(c[2]), "+f"(c[3])
        : "r"(a[0]), "r"(a[1]), "r"(a[2]), "r"(a[3]), "r"(b[0]), "r"(b[1]));
}

#define ASTR 36   // A smem row stride (floats): 36 mod 32 = 4 -> conflict-free frag loads
#define BSTR 136  // B smem row stride (floats): 136 mod 32 = 8 -> conflict-free frag loads
#define A_STAGE (128*ASTR)          // 4608 floats
#define B_STAGE (32*BSTR)           // 4352 floats
#define GEMM_SMEM ((2*A_STAGE + 2*B_STAGE)*4)   // 71680 bytes

__global__ __launch_bounds__(256) void mma_gemm_kernel(
    const float* __restrict__ A, const float* __restrict__ W,
    const float* __restrict__ bias, float* __restrict__ C,
    int Ndim, int Kdim, int act)
{
    extern __shared__ float sm[];
    float* Asm = sm;                  // [2][128][ASTR]
    float* Bsm = sm + 2 * A_STAGE;    // [2][32][BSTR]

    const int tid  = threadIdx.x;
    const int lane = tid & 31, wid = tid >> 5;
    const int wm0  = (wid >> 2) * 64;     // warp m origin (0,64)
    const int wn0  = (wid & 3)  * 32;     // warp n origin (0,32,64,96)
    const int tq   = lane >> 2, tr = lane & 3;
    const int bm   = blockIdx.y * 128, bn = blockIdx.x * 128;

    const int ar = tid >> 3, ac = (tid & 7) * 4;    // A gmem coords (32 rows/pass)
    const int br = tid >> 5, bc = (tid & 31) * 4;   // B gmem coords (8 rows/pass)

    float4 areg[4], breg[4];
    float acc[4][4][4];
    #pragma unroll
    for (int i = 0; i < 4; i++)
        #pragma unroll
        for (int j = 0; j < 4; j++)
            #pragma unroll
            for (int q = 0; q < 4; q++) acc[i][j][q] = 0.f;

    const int KC = Kdim >> 5;

    // ---- prologue: load tile 0 ----
    #pragma unroll
    for (int p = 0; p < 4; p++)
        areg[p] = *(const float4*)(A + (size_t)(bm + ar + p * 32) * Kdim + ac);
    #pragma unroll
    for (int p = 0; p < 4; p++)
        breg[p] = *(const float4*)(W + (size_t)(br + p * 8) * Ndim + bn + bc);
    #pragma unroll
    for (int p = 0; p < 4; p++) {
        uint4 u;
        u.x = f2tf32(areg[p].x); u.y = f2tf32(areg[p].y);
        u.z = f2tf32(areg[p].z); u.w = f2tf32(areg[p].w);
        *(uint4*)(Asm + (ar + p * 32) * ASTR + ac) = u;
    }
    #pragma unroll
    for (int p = 0; p < 4; p++) {
        uint4 u;
        u.x = f2tf32(breg[p].x); u.y = f2tf32(breg[p].y);
        u.z = f2tf32(breg[p].z); u.w = f2tf32(breg[p].w);
        *(uint4*)(Bsm + (br + p * 8) * BSTR + bc) = u;
    }
    __syncthreads();

    for (int it = 0; it < KC; it++) {
        const int cur = it & 1;
        if (it + 1 < KC) {
            const int k0 = (it + 1) << 5;
            #pragma unroll
            for (int p = 0; p < 4; p++)
                areg[p] = *(const float4*)(A + (size_t)(bm + ar + p * 32) * Kdim + k0 + ac);
            #pragma unroll
            for (int p = 0; p < 4; p++)
                breg[p] = *(const float4*)(W + (size_t)(k0 + br + p * 8) * Ndim + bn + bc);
        }
        const float* Ab = Asm + cur * A_STAGE;
        const float* Bb = Bsm + cur * B_STAGE;
        #pragma unroll
        for (int ks = 0; ks < 4; ks++) {
            const int k = ks * 8;
            uint32_t af[4][4], bf[4][2];
            #pragma unroll
            for (int mf = 0; mf < 4; mf++) {
                const int row = wm0 + mf * 16 + tq;
                af[mf][0] = __float_as_uint(Ab[row * ASTR + k + tr]);
                af[mf][1] = __float_as_uint(Ab[(row + 8) * ASTR + k + tr]);
                af[mf][2] = __float_as_uint(Ab[row * ASTR + k + tr + 4]);
                af[mf][3] = __float_as_uint(Ab[(row + 8) * ASTR + k + tr + 4]);
            }
            #pragma unroll
            for (int nf = 0; nf < 4; nf++) {
                const int col = wn0 + nf * 8 + tq;
                bf[nf][0] = __float_as_uint(Bb[(k + tr) * BSTR + col]);
                bf[nf][1] = __float_as_uint(Bb[(k + tr + 4) * BSTR + col]);
            }
            #pragma unroll
            for (int mf = 0; mf < 4; mf++)
                #pragma unroll
                for (int nf = 0; nf < 4; nf++)
                    mma_m16n8k8(acc[mf][nf], af[mf], bf[nf]);
        }
        if (it + 1 < KC) {
            const int nxt = (it + 1) & 1;
            float* An = Asm + nxt * A_STAGE;
            float* Bn = Bsm + nxt * B_STAGE;
            #pragma unroll
            for (int p = 0; p < 4; p++) {
                uint4 u;
                u.x = f2tf32(areg[p].x); u.y = f2tf32(areg[p].y);
                u.z = f2tf32(areg[p].z); u.w = f2tf32(areg[p].w);
                *(uint4*)(An + (ar + p * 32) * ASTR + ac) = u;
            }
            #pragma unroll
            for (int p = 0; p < 4; p++) {
                uint4 u;
                u.x = f2tf32(breg[p].x); u.y = f2tf32(breg[p].y);
                u.z = f2tf32(breg[p].z); u.w = f2tf32(breg[p].w);
                *(uint4*)(Bn + (br + p * 8) * BSTR + bc) = u;
            }
            __syncthreads();
        }
    }

    // ---- epilogue: direct float2 stores with fused bias/sigmoid ----
    #pragma unroll
    for (int mf = 0; mf < 4; mf++) {
        const int row = bm + wm0 + mf * 16 + tq;
        #pragma unroll
        for (int nf = 0; nf < 4; nf++) {
            const int col = bn + wn0 + nf * 8 + 2 * tr;
            float b0 = 0.f, b1 = 0.f;
            if (bias) { b0 = bias[col]; b1 = bias[col + 1]; }
            float v0 = acc[mf][nf][0] + b0;
            float v1 = acc[mf][nf][1] + b1;
            float v2 = acc[mf][nf][2] + b0;
            float v3 = acc[mf][nf][3] + b1;
            if (act == 1) {
                v0 = 1.f / (1.f + expf(-v0));
                v1 = 1.f / (1.f + expf(-v1));
                v2 = 1.f / (1.f + expf(-v2));
                v3 = 1.f / (1.f + expf(-v3));
            }
            *(float2*)(C + (size_t)row * Ndim + col)       = make_float2(v0, v1);
            *(float2*)(C + (size_t)(row + 8) * Ndim + col) = make_float2(v2, v3);
        }
    }
}

// ---------------- block reductions (256 threads) ----------------
__device__ __forceinline__ float block_reduce_sum(float v) {
    __shared__ float sh[8];
    __shared__ float res;
    __syncthreads();
    #pragma unroll
    for (int o = 16; o > 0; o >>= 1) v += __shfl_down_sync(0xffffffffu, v, o);
    int lane = threadIdx.x & 31, w = threadIdx.x >> 5;
    if (lane == 0) sh[w] = v;
    __syncthreads();
    if (w == 0) {
        v = (lane < 8) ? sh[lane] : 0.f;
        #pragma unroll
        for (int o = 4; o > 0; o >>= 1) v += __shfl_down_sync(0xffffffffu, v, o);
        if (lane == 0) res = v;
    }
    __syncthreads();
    return res;
}
__device__ __forceinline__ float block_reduce_max(float v) {
    __shared__ float sh[8];
    __shared__ float res;
    __syncthreads();
    #pragma unroll
    for (int o = 16; o > 0; o >>= 1) v = fmaxf(v, __shfl_down_sync(0xffffffffu, v, o));
    int lane = threadIdx.x & 31, w = threadIdx.x >> 5;
    if (lane == 0) sh[w] = v;
    __syncthreads();
    if (w == 0) {
        v = (lane < 8) ? sh[lane] : -1e30f;
        #pragma unroll
        for (int o = 4; o > 0; o >>= 1) v = fmaxf(v, __shfl_down_sync(0xffffffffu, v, o));
        if (lane == 0) res = v;
    }
    __syncthreads();
    return res;
}

// ---------------- LayerNorm ----------------
__global__ __launch_bounds__(256) void ln_kernel(const float* __restrict__ x,
                                                 const float* __restrict__ w,
                                                 float* __restrict__ out) {
    int row = blockIdx.x;
    const float* xr = x + (size_t)row * D_;
    float* orow = out + (size_t)row * D_;
    float lv[3];
    float s = 0.f;
    #pragma unroll
    for (int i = 0; i < 3; i++) { lv[i] = xr[threadIdx.x + i*256]; s += lv[i]; }
    float mean = block_reduce_sum(s) * (1.f / D_);
    float vs = 0.f;
    #pragma unroll
    for (int i = 0; i < 3; i++) { float d = lv[i] - mean; vs += d * d; }
    float var = block_reduce_sum(vs) * (1.f / D_);
    float rstd = rsqrtf(var + EPS_);
    #pragma unroll
    for (int i = 0; i < 3; i++) {
        int c = threadIdx.x + i*256;
        float y = (lv[i] - mean) * rstd;
        if (w) y *= w[c];
        orow[c] = y;
    }
}

// ---------------- attention scores ----------------
__global__ __launch_bounds__(256) void scores_kernel(const float* __restrict__ q,
                                                     const float* __restrict__ k,
                                                     const float* __restrict__ z,
                                                     float* __restrict__ p) {
    __shared__ float Qs[64][49];
    __shared__ float Ks[64][49];
    const int batch = blockIdx.z;
    const int h = batch / B_, b = batch % B_;
    const int qi0 = blockIdx.y * 64, ki0 = blockIdx.x * 64;
    const size_t qbase = ((size_t)(b * N_) + qi0) * D_ + h * HD_;
    const size_t kbase = ((size_t)(b * N_) + ki0) * D_ + h * HD_;
    const int tid = threadIdx.x, tx = tid & 15, ty = tid >> 4;
    for (int l = tid; l < 64 * 48; l += 256) {
        int r = l / 48, c = l % 48;
        Qs[r][c] = q[qbase + (size_t)r * D_ + c];
        Ks[r][c] = k[kbase + (size_t)r * D_ + c];
    }
    __syncthreads();
    float acc[4][4] = {};
    #pragma unroll 8
    for (int kk = 0; kk < 48; kk++) {
        float av[4], wv[4];
        #pragma unroll
        for (int i = 0; i < 4; i++) av[i] = Qs[ty * 4 + i][kk];
        #pragma unroll
        for (int j = 0; j < 4; j++) wv[j] = Ks[tx * 4 + j][kk];
        #pragma unroll
        for (int i = 0; i < 4; i++)
            #pragma unroll
            for (int j = 0; j < 4; j++)
                acc[i][j] = fmaf(av[i], wv[j], acc[i][j]);
    }
    const float scale = 0.14433756729740643f;
    const size_t pbase = ((size_t)batch * N_ + qi0) * N_ + ki0;
    #pragma unroll
    for (int i = 0; i < 4; i++)
        #pragma unroll
        for (int j = 0; j < 4; j++) {
            size_t off = pbase + (size_t)(ty * 4 + i) * N_ + tx * 4 + j;
            p[off] = acc[i][j] * scale + z[off];
        }
}

// ---------------- row softmax ----------------
__global__ __launch_bounds__(256) void softmax_kernel(float* __restrict__ p) {
    const size_t row = blockIdx.x;
    float* pr = p + row * (size_t)N_;
    float lv[4];
    float mx = -1e30f;
    #pragma unroll
    for (int i = 0; i < 4; i++) { lv[i] = pr[threadIdx.x + i*256]; mx = fmaxf(mx, lv[i]); }
    mx = block_reduce_max(mx);
    float s = 0.f;
    #pragma unroll
    for (int i = 0; i < 4; i++) { lv[i] = expf(lv[i] - mx); s += lv[i]; }
    s = block_reduce_sum(s);
    float inv = 1.f / s;
    #pragma unroll
    for (int i = 0; i < 4; i++) pr[threadIdx.x + i*256] = lv[i] * inv;
}

// ---------------- P @ V ----------------
__global__ __launch_bounds__(256) void attn_o_kernel(const float* __restrict__ p,
                                                     const float* __restrict__ v,
                                                     float* __restrict__ o) {
    __shared__ float Ps[16][64];
    __shared__ float Vs[16][48];
    const int batch = blockIdx.z;
    const int h = batch / B_, b = batch % B_;
    const int qi0 = blockIdx.y * 64;
    const int tid = threadIdx.x, tx = tid & 15, ty = tid >> 4;
    float acc[4][3] = {};
    const size_t pbase = ((size_t)batch * N_ + qi0) * N_;
    const size_t vbase = ((size_t)(b * N_)) * D_ + h * HD_;
    for (int k0 = 0; k0 < N_; k0 += 16) {
        for (int l = tid; l < 64 * 16; l += 256) {
            int r = l >> 4, c = l & 15;
            Ps[c][r] = p[pbase + (size_t)r * N_ + k0 + c];
        }
        for (int l = tid; l < 16 * 48; l += 256) {
            int r = l / 48, c = l % 48;
            Vs[r][c] = v[vbase + (size_t)(k0 + r) * D_ + c];
        }
        __syncthreads();
        #pragma unroll
        for (int kk = 0; kk < 16; kk++) {
            float av[4], wv[3];
            #pragma unroll
            for (int i = 0; i < 4; i++) av[i] = Ps[kk][ty * 4 + i];
            #pragma unroll
            for (int j = 0; j < 3; j++) wv[j] = Vs[kk][tx * 3 + j];
            #pragma unroll
            for (int i = 0; i < 4; i++)
                #pragma unroll
                for (int j = 0; j < 3; j++)
                    acc[i][j] = fmaf(av[i], wv[j], acc[i][j]);
        }
        __syncthreads();
    }
    #pragma unroll
    for (int i = 0; i < 4; i++)
        #pragma unroll
        for (int j = 0; j < 3; j++)
            o[((size_t)(b * N_) + qi0 + ty * 4 + i) * D_ + h * HD_ + tx * 3 + j] = acc[i][j];
}

// ---------------- elementwise fusions ----------------
__global__ void ew_adaln_kernel(const float* __restrict__ an, const float* __restrict__ sig,
                                const float* __restrict__ c2, float* __restrict__ out, int n) {
    int i = blockIdx.x * blockDim.x + threadIdx.x;
    if (i < n) out[i] = an[i] * sig[i] + c2[i];
}
__global__ void ew_mul_kernel(const float* __restrict__ a, const float* __restrict__ b,
                              float* __restrict__ out, int n) {
    int i = blockIdx.x * blockDim.x + threadIdx.x;
    if (i < n) out[i] = a[i] * b[i];
}
__global__ void ew_gate_add_kernel(const float* __restrict__ base, const float* __restrict__ g,
                                   const float* __restrict__ x, float* __restrict__ out, int n) {
    int i = blockIdx.x * blockDim.x + threadIdx.x;
    if (i < n) out[i] = base[i] + g[i] * x[i];
}
__global__ void ew_swiglu_kernel(const float* __restrict__ sw, const float* __restrict__ ab,
                                 float* __restrict__ out, int n) {
    int i = blockIdx.x * blockDim.x + threadIdx.x;
    if (i < n) {
        int row = i / HID_, j = i - row * HID_;
        float u  = sw[(size_t)row * (2 * HID_) + j];
        float gt = sw[(size_t)row * (2 * HID_) + HID_ + j];
        float sg = 1.f / (1.f + expf(-gt));
        out[i] = gt * sg * u * ab[i];
    }
}

// ---------------- host orchestration ----------------
static float* sym(const void* s) { void* p = nullptr; cudaGetSymbolAddress(&p, s); return (float*)p; }

static void run_gemm(const float* A, const float* W, const float* bias,
                     float* C, int Ndim, int Kdim, int act) {
    mma_gemm_kernel<<<dim3(Ndim / 128, M_ / 128), 256, GEMM_SMEM>>>(A, W, bias, C, Ndim, Kdim, act);
}

extern "C" void kernel_launch(void* const* d_in, const int* in_sizes, int n_in,
                              void* d_out, int out_size) {
    const float* a          = (const float*)d_in[0];
    const float* s          = (const float*)d_in[1];
    const float* z          = (const float*)d_in[2];
    const float* ad1_snw    = (const float*)d_in[3];
    const float* ad1_ssw    = (const float*)d_in[4];
    const float* ad1_ssb    = (const float*)d_in[5];
    const float* ad1_sbw    = (const float*)d_in[6];
    const float* q_w        = (const float*)d_in[7];
    const float* q_b        = (const float*)d_in[8];
    const float* k_w        = (const float*)d_in[9];
    const float* v_w        = (const float*)d_in[10];
    const float* g_w        = (const float*)d_in[11];
    const float* o_w        = (const float*)d_in[12];
    const float* outproj_w  = (const float*)d_in[13];
    const float* outproj_b  = (const float*)d_in[14];
    const float* ad2_snw    = (const float*)d_in[15];
    const float* ad2_ssw    = (const float*)d_in[16];
    const float* ad2_ssb    = (const float*)d_in[17];
    const float* ad2_sbw    = (const float*)d_in[18];
    const float* swish_w    = (const float*)d_in[19];
    const float* a2b_w      = (const float*)d_in[20];
    const float* b2a_w      = (const float*)d_in[21];
    const float* op_w       = (const float*)d_in[22];
    const float* op_b       = (const float*)d_in[23];
    float* out = (float*)d_out;

    cudaFuncSetAttribute(mma_gemm_kernel, cudaFuncAttributeMaxDynamicSharedMemorySize, GEMM_SMEM);

    float *an = sym(g_an), *sn = sym(g_sn), *c1 = sym(g_c1), *c2 = sym(g_c2);
    float *bm = sym(g_bm), *qb = sym(g_q), *kb = sym(g_k), *vb = sym(g_v);
    float *gt = sym(g_gt), *ob = sym(g_o), *og = sym(g_og), *xw = sym(g_xw);
    float *sg = sym(g_sig), *anew = sym(g_anew), *hb = sym(g_hb);
    float *sw = sym(g_sw), *ab = sym(g_ab), *hid = sym(g_hid), *p = sym(g_p);

    const int nMD = M_ * D_;
    const int nMH = M_ * HID_;
    const int EW = 256;

    // ===== adaLN 1 =====
    ln_kernel<<<M_, 256>>>(a, nullptr, an);
    ln_kernel<<<M_, 256>>>(s, ad1_snw, sn);
    run_gemm(sn, ad1_ssw, ad1_ssb, c1, D_, D_, 1);
    run_gemm(sn, ad1_sbw, nullptr, c2, D_, D_, 0);
    ew_adaln_kernel<<<nMD / EW, EW>>>(an, c1, c2, bm, nMD);

    // ===== QKVG projections =====
    run_gemm(bm, q_w, q_b,     qb, D_, D_, 0);
    run_gemm(bm, k_w, nullptr, kb, D_, D_, 0);
    run_gemm(bm, v_w, nullptr, vb, D_, D_, 0);
    run_gemm(bm, g_w, nullptr, gt, D_, D_, 1);

    // ===== attention =====
    scores_kernel<<<dim3(N_/64, N_/64, H_*B_), 256>>>(qb, kb, z, p);
    softmax_kernel<<<H_*B_*N_, 256>>>(p);
    attn_o_kernel<<<dim3(1, N_/64, H_*B_), 256>>>(p, vb, ob);

    // ===== output projection + gated residual =====
    ew_mul_kernel<<<nMD / EW, EW>>>(ob, gt, og, nMD);
    run_gemm(og, o_w, nullptr, xw, D_, D_, 0);
    run_gemm(s, outproj_w, outproj_b, sg, D_, D_, 1);
    ew_gate_add_kernel<<<nMD / EW, EW>>>(a, sg, xw, anew, nMD);

    // ===== adaLN 2 =====
    ln_kernel<<<M_, 256>>>(anew, nullptr, an);
    ln_kernel<<<M_, 256>>>(s, ad2_snw, sn);
    run_gemm(sn, ad2_ssw, ad2_ssb, c1, D_, D_, 1);
    run_gemm(sn, ad2_sbw, nullptr, c2, D_, D_, 0);
    ew_adaln_kernel<<<nMD / EW, EW>>>(an, c1, c2, bm, nMD);

    // ===== MLP =====
    run_gemm(bm, swish_w, nullptr, sw, 2*HID_, D_, 0);
    run_gemm(bm, a2b_w,   nullptr, ab, HID_, D_, 0);
    ew_swiglu_kernel<<<nMH / EW, EW>>>(sw, ab, hid, nMH);
    run_gemm(hid, b2a_w, nullptr, hb, D_, HID_, 0);
    run_gemm(s, op_w, op_b, sg, D_, D_, 1);
    ew_gate_add_kernel<<<nMD / EW, EW>>>(anew, sg, hb, out, nMD);
}

// round 4
// speedup vs baseline: 4.0397x; 1.6485x over previous
#include <cuda_runtime.h>
#include <math.h>
#include <stdint.h>

#define B_   2
#define N_   1024
#define D_   768
#define H_   16
#define HD_  48
#define HID_ 1536
#define M_   (B_*N_)      // 2048
#define EPS_ 1e-5f

// ---------------- scratch (static device buffers; no allocation) ----------------
__device__ float g_an  [M_*D_];
__device__ float g_sn  [M_*D_];
__device__ float g_c1  [M_*D_];
__device__ float g_c2  [M_*D_];
__device__ float g_bm  [M_*D_];
__device__ float g_q   [M_*D_];
__device__ float g_k   [M_*D_];
__device__ float g_v   [M_*D_];
__device__ float g_gt  [M_*D_];
__device__ float g_o   [M_*D_];
__device__ float g_og  [M_*D_];
__device__ float g_xw  [M_*D_];
__device__ float g_sig [M_*D_];
__device__ float g_anew[M_*D_];
__device__ float g_hb  [M_*D_];
__device__ float g_sw  [M_*2*HID_];
__device__ float g_ab  [M_*HID_];
__device__ float g_hid [M_*HID_];

// =================================================================================
// tf32 helpers
// =================================================================================
__device__ __forceinline__ uint32_t f2tf32(float f) {
    uint32_t u;
    asm("cvt.rna.tf32.f32 %0, %1;" : "=r"(u) : "f"(f));
    return u;
}
__device__ __forceinline__ void mma_m16n8k8(float* c, const uint32_t* a, const uint32_t* b) {
    asm volatile(
        "mma.sync.aligned.m16n8k8.row.col.f32.tf32.tf32.f32 "
        "{%0,%1,%2,%3}, {%4,%5,%6,%7}, {%8,%9}, {%0,%1,%2,%3};"
        : "+f"(c[0]), "+f"(c[1]), "+f"(c[2]), "+f"(c[3])
        : "r"(a[0]), "r"(a[1]), "r"(a[2]), "r"(a[3]), "r"(b[0]), "r"(b[1]));
}

// =================================================================================
// multi-slice tf32 GEMM: per z-slice C[M,N]=A[M,K]@W[K,N] (+bias)(+sigmoid)
// 128x128x32 block tile, 256 thr, 8 warps (2x4), warp tile 64x32.
// =================================================================================
struct GSlice {
    const float* A; const float* W; const float* bias; float* C;
    int K; int Wstride; int Cstride; int act;
};
struct GPack { GSlice s[4]; };

#define ASTR 36
#define BSTR 136
#define A_STAGE (128*ASTR)
#define B_STAGE (32*BSTR)
#define GEMM_SMEM ((2*A_STAGE + 2*B_STAGE)*4)   // 71680 bytes

__global__ __launch_bounds__(256) void mma_gemm_kernel(GPack pk, int Ndim)
{
    extern __shared__ float sm[];
    float* Asm = sm;
    float* Bsm = sm + 2 * A_STAGE;

    const GSlice sl = pk.s[blockIdx.z];
    const float* A = sl.A;
    const float* W = sl.W;
    const int Kdim = sl.K, Wstr = sl.Wstride, Cstr = sl.Cstride, act = sl.act;

    const int tid  = threadIdx.x;
    const int lane = tid & 31, wid = tid >> 5;
    const int wm0  = (wid >> 2) * 64;
    const int wn0  = (wid & 3)  * 32;
    const int tq   = lane >> 2, tr = lane & 3;
    const int bm   = blockIdx.y * 128, bn = blockIdx.x * 128;

    const int ar = tid >> 3, ac = (tid & 7) * 4;
    const int br = tid >> 5, bc = (tid & 31) * 4;

    float4 areg[4], breg[4];
    float acc[4][4][4];
    #pragma unroll
    for (int i = 0; i < 4; i++)
        #pragma unroll
        for (int j = 0; j < 4; j++)
            #pragma unroll
            for (int q = 0; q < 4; q++) acc[i][j][q] = 0.f;

    const int KC = Kdim >> 5;

    #pragma unroll
    for (int p = 0; p < 4; p++)
        areg[p] = *(const float4*)(A + (size_t)(bm + ar + p * 32) * Kdim + ac);
    #pragma unroll
    for (int p = 0; p < 4; p++)
        breg[p] = *(const float4*)(W + (size_t)(br + p * 8) * Wstr + bn + bc);
    #pragma unroll
    for (int p = 0; p < 4; p++) {
        uint4 u;
        u.x = f2tf32(areg[p].x); u.y = f2tf32(areg[p].y);
        u.z = f2tf32(areg[p].z); u.w = f2tf32(areg[p].w);
        *(uint4*)(Asm + (ar + p * 32) * ASTR + ac) = u;
    }
    #pragma unroll
    for (int p = 0; p < 4; p++) {
        uint4 u;
        u.x = f2tf32(breg[p].x); u.y = f2tf32(breg[p].y);
        u.z = f2tf32(breg[p].z); u.w = f2tf32(breg[p].w);
        *(uint4*)(Bsm + (br + p * 8) * BSTR + bc) = u;
    }
    __syncthreads();

    for (int it = 0; it < KC; it++) {
        const int cur = it & 1;
        if (it + 1 < KC) {
            const int k0 = (it + 1) << 5;
            #pragma unroll
            for (int p = 0; p < 4; p++)
                areg[p] = *(const float4*)(A + (size_t)(bm + ar + p * 32) * Kdim + k0 + ac);
            #pragma unroll
            for (int p = 0; p < 4; p++)
                breg[p] = *(const float4*)(W + (size_t)(k0 + br + p * 8) * Wstr + bn + bc);
        }
        const float* Ab = Asm + cur * A_STAGE;
        const float* Bb = Bsm + cur * B_STAGE;
        #pragma unroll
        for (int ks = 0; ks < 4; ks++) {
            const int k = ks * 8;
            uint32_t af[4][4], bf[4][2];
            #pragma unroll
            for (int mf = 0; mf < 4; mf++) {
                const int row = wm0 + mf * 16 + tq;
                af[mf][0] = __float_as_uint(Ab[row * ASTR + k + tr]);
                af[mf][1] = __float_as_uint(Ab[(row + 8) * ASTR + k + tr]);
                af[mf][2] = __float_as_uint(Ab[row * ASTR + k + tr + 4]);
                af[mf][3] = __float_as_uint(Ab[(row + 8) * ASTR + k + tr + 4]);
            }
            #pragma unroll
            for (int nf = 0; nf < 4; nf++) {
                const int col = wn0 + nf * 8 + tq;
                bf[nf][0] = __float_as_uint(Bb[(k + tr) * BSTR + col]);
                bf[nf][1] = __float_as_uint(Bb[(k + tr + 4) * BSTR + col]);
            }
            #pragma unroll
            for (int mf = 0; mf < 4; mf++)
                #pragma unroll
                for (int nf = 0; nf < 4; nf++)
                    mma_m16n8k8(acc[mf][nf], af[mf], bf[nf]);
        }
        if (it + 1 < KC) {
            const int nxt = (it + 1) & 1;
            float* An = Asm + nxt * A_STAGE;
            float* Bn = Bsm + nxt * B_STAGE;
            #pragma unroll
            for (int p = 0; p < 4; p++) {
                uint4 u;
                u.x = f2tf32(areg[p].x); u.y = f2tf32(areg[p].y);
                u.z = f2tf32(areg[p].z); u.w = f2tf32(areg[p].w);
                *(uint4*)(An + (ar + p * 32) * ASTR + ac) = u;
            }
            #pragma unroll
            for (int p = 0; p < 4; p++) {
                uint4 u;
                u.x = f2tf32(breg[p].x); u.y = f2tf32(breg[p].y);
                u.z = f2tf32(breg[p].z); u.w = f2tf32(breg[p].w);
                *(uint4*)(Bn + (br + p * 8) * BSTR + bc) = u;
            }
            __syncthreads();
        }
    }

    #pragma unroll
    for (int mf = 0; mf < 4; mf++) {
        const int row = bm + wm0 + mf * 16 + tq;
        #pragma unroll
        for (int nf = 0; nf < 4; nf++) {
            const int col = bn + wn0 + nf * 8 + 2 * tr;
            float b0 = 0.f, b1 = 0.f;
            if (sl.bias) { b0 = sl.bias[col]; b1 = sl.bias[col + 1]; }
            float v0 = acc[mf][nf][0] + b0;
            float v1 = acc[mf][nf][1] + b1;
            float v2 = acc[mf][nf][2] + b0;
            float v3 = acc[mf][nf][3] + b1;
            if (act == 1) {
                v0 = 1.f / (1.f + __expf(-v0));
                v1 = 1.f / (1.f + __expf(-v1));
                v2 = 1.f / (1.f + __expf(-v2));
                v3 = 1.f / (1.f + __expf(-v3));
            }
            *(float2*)(sl.C + (size_t)row * Cstr + col)       = make_float2(v0, v1);
            *(float2*)(sl.C + (size_t)(row + 8) * Cstr + col) = make_float2(v2, v3);
        }
    }
}

// =================================================================================
// flash attention, tf32 mma. One CTA = 64 q-rows of one (h,b). 4 warps, 128 thr.
// Warp tile 16x64 (rows fully in-warp -> shuffle-only softmax).
// =================================================================================
#define QSTR 52
#define PSTR 68
#define FA_Q  0
#define FA_K  3328
#define FA_V  6656
#define FA_P  9984
#define FA_SMEM ((9984 + 64*PSTR)*4)   // 57344 bytes

__global__ __launch_bounds__(128) void flash_attn_kernel(
    const float* __restrict__ q, const float* __restrict__ k,
    const float* __restrict__ v, const float* __restrict__ z,
    float* __restrict__ o)
{
    extern __shared__ float fsm[];
    float* Qs = fsm + FA_Q;
    float* Ks = fsm + FA_K;
    float* Vs = fsm + FA_V;
    float* Ps = fsm + FA_P;

    const int tid = threadIdx.x, lane = tid & 31, wq = tid >> 5;
    const int tq = lane >> 2, tr = lane & 3;
    const int qt = blockIdx.x;            // 0..15
    const int hb = blockIdx.y;            // h*B + b
    const int h = hb / B_, b = hb % B_;
    const int q0 = qt * 64;
    const float scale = 0.14433756729740643f;   // 1/sqrt(48)

    // load Q tile (64 x 48) -> smem tf32
    for (int e = tid; e < 64 * 12; e += 128) {
        const int r = e / 12, c4 = (e % 12) * 4;
        const float4 vq = *(const float4*)(q + ((size_t)(b * N_) + q0 + r) * D_ + h * HD_ + c4);
        uint4 u;
        u.x = f2tf32(vq.x); u.y = f2tf32(vq.y); u.z = f2tf32(vq.z); u.w = f2tf32(vq.w);
        *(uint4*)(Qs + r * QSTR + c4) = u;
    }
    __syncthreads();

    // preload Q fragments (rows wq*16+tq, +8)
    const int rowa = wq * 16 + tq;
    uint32_t qf[6][4];
    #pragma unroll
    for (int kk = 0; kk < 6; kk++) {
        qf[kk][0] = __float_as_uint(Qs[rowa * QSTR + kk * 8 + tr]);
        qf[kk][1] = __float_as_uint(Qs[(rowa + 8) * QSTR + kk * 8 + tr]);
        qf[kk][2] = __float_as_uint(Qs[rowa * QSTR + kk * 8 + tr + 4]);
        qf[kk][3] = __float_as_uint(Qs[(rowa + 8) * QSTR + kk * 8 + tr + 4]);
    }

    float m0 = -1e30f, m1 = -1e30f, l0 = 0.f, l1 = 0.f;
    float O[6][4];
    #pragma unroll
    for (int i = 0; i < 6; i++)
        #pragma unroll
        for (int j = 0; j < 4; j++) O[i][j] = 0.f;

    for (int t = 0; t < 16; t++) {
        __syncthreads();   // previous tile's Ks/Vs reads complete
        for (int e = tid; e < 64 * 12; e += 128) {
            const int r = e / 12, c4 = (e % 12) * 4;
            const size_t gof = ((size_t)(b * N_) + t * 64 + r) * D_ + h * HD_ + c4;
            const float4 vk = *(const float4*)(k + gof);
            const float4 vv = *(const float4*)(v + gof);
            uint4 uk, uv;
            uk.x = f2tf32(vk.x); uk.y = f2tf32(vk.y); uk.z = f2tf32(vk.z); uk.w = f2tf32(vk.w);
            uv.x = f2tf32(vv.x); uv.y = f2tf32(vv.y); uv.z = f2tf32(vv.z); uv.w = f2tf32(vv.w);
            *(uint4*)(Ks + r * QSTR + c4) = uk;
            *(uint4*)(Vs + r * QSTR + c4) = uv;
        }
        __syncthreads();

        // S = Q @ K^T  (warp rows 16, cols 64)
        float c[8][4];
        #pragma unroll
        for (int nf = 0; nf < 8; nf++)
            #pragma unroll
            for (int j = 0; j < 4; j++) c[nf][j] = 0.f;
        #pragma unroll
        for (int nf = 0; nf < 8; nf++) {
            #pragma unroll
            for (int kk = 0; kk < 6; kk++) {
                uint32_t bf[2];
                bf[0] = __float_as_uint(Ks[(nf * 8 + tq) * QSTR + kk * 8 + tr]);
                bf[1] = __float_as_uint(Ks[(nf * 8 + tq) * QSTR + kk * 8 + tr + 4]);
                mma_m16n8k8(c[nf], qf[kk], bf);
            }
        }

        // scale + z, row max
        float mx0 = -1e30f, mx1 = -1e30f;
        const size_t zb0 = (((size_t)hb) * N_ + q0 + rowa) * N_ + t * 64 + 2 * tr;
        #pragma unroll
        for (int nf = 0; nf < 8; nf++) {
            const float2 z0 = *(const float2*)(z + zb0 + nf * 8);
            const float2 z1 = *(const float2*)(z + zb0 + (size_t)8 * N_ + nf * 8);
            c[nf][0] = fmaf(c[nf][0], scale, z0.x);
            c[nf][1] = fmaf(c[nf][1], scale, z0.y);
            c[nf][2] = fmaf(c[nf][2], scale, z1.x);
            c[nf][3] = fmaf(c[nf][3], scale, z1.y);
            mx0 = fmaxf(mx0, fmaxf(c[nf][0], c[nf][1]));
            mx1 = fmaxf(mx1, fmaxf(c[nf][2], c[nf][3]));
        }
        mx0 = fmaxf(mx0, __shfl_xor_sync(0xffffffffu, mx0, 1));
        mx0 = fmaxf(mx0, __shfl_xor_sync(0xffffffffu, mx0, 2));
        mx1 = fmaxf(mx1, __shfl_xor_sync(0xffffffffu, mx1, 1));
        mx1 = fmaxf(mx1, __shfl_xor_sync(0xffffffffu, mx1, 2));
        const float mn0 = fmaxf(m0, mx0), mn1 = fmaxf(m1, mx1);
        const float a0 = __expf(m0 - mn0), a1 = __expf(m1 - mn1);

        // P = exp(S - m), write tf32 P to smem, row sums
        float rs0 = 0.f, rs1 = 0.f;
        #pragma unroll
        for (int nf = 0; nf < 8; nf++) {
            const float p0 = __expf(c[nf][0] - mn0);
            const float p1 = __expf(c[nf][1] - mn0);
            const float p2 = __expf(c[nf][2] - mn1);
            const float p3 = __expf(c[nf][3] - mn1);
            rs0 += p0 + p1; rs1 += p2 + p3;
            uint2 u0, u1;
            u0.x = f2tf32(p0); u0.y = f2tf32(p1);
            u1.x = f2tf32(p2); u1.y = f2tf32(p3);
            *(uint2*)(Ps + rowa * PSTR + nf * 8 + 2 * tr)       = u0;
            *(uint2*)(Ps + (rowa + 8) * PSTR + nf * 8 + 2 * tr) = u1;
        }
        rs0 += __shfl_xor_sync(0xffffffffu, rs0, 1);
        rs0 += __shfl_xor_sync(0xffffffffu, rs0, 2);
        rs1 += __shfl_xor_sync(0xffffffffu, rs1, 1);
        rs1 += __shfl_xor_sync(0xffffffffu, rs1, 2);
        l0 = l0 * a0 + rs0;
        l1 = l1 * a1 + rs1;
        m0 = mn0; m1 = mn1;

        // rescale O accumulators
        #pragma unroll
        for (int nf = 0; nf < 6; nf++) {
            O[nf][0] *= a0; O[nf][1] *= a0;
            O[nf][2] *= a1; O[nf][3] *= a1;
        }
        __syncwarp();

        // O += P @ V
        #pragma unroll
        for (int ks = 0; ks < 8; ks++) {
            uint32_t pf[4];
            pf[0] = __float_as_uint(Ps[rowa * PSTR + ks * 8 + tr]);
            pf[1] = __float_as_uint(Ps[(rowa + 8) * PSTR + ks * 8 + tr]);
            pf[2] = __float_as_uint(Ps[rowa * PSTR + ks * 8 + tr + 4]);
            pf[3] = __float_as_uint(Ps[(rowa + 8) * PSTR + ks * 8 + tr + 4]);
            #pragma unroll
            for (int nf = 0; nf < 6; nf++) {
                uint32_t vf[2];
                vf[0] = __float_as_uint(Vs[(ks * 8 + tr) * QSTR + nf * 8 + tq]);
                vf[1] = __float_as_uint(Vs[(ks * 8 + tr + 4) * QSTR + nf * 8 + tq]);
                mma_m16n8k8(O[nf], pf, vf);
            }
        }
    }

    // normalize and store
    const float il0 = 1.f / l0, il1 = 1.f / l1;
    const size_t ob0 = ((size_t)(b * N_) + q0 + rowa) * D_ + h * HD_ + 2 * tr;
    #pragma unroll
    for (int nf = 0; nf < 6; nf++) {
        *(float2*)(o + ob0 + nf * 8)               = make_float2(O[nf][0] * il0, O[nf][1] * il0);
        *(float2*)(o + ob0 + (size_t)8 * D_ + nf * 8) = make_float2(O[nf][2] * il1, O[nf][3] * il1);
    }
}

// ---------------- block reductions (256 threads) ----------------
__device__ __forceinline__ float block_reduce_sum(float v) {
    __shared__ float sh[8];
    __shared__ float res;
    __syncthreads();
    #pragma unroll
    for (int o = 16; o > 0; o >>= 1) v += __shfl_down_sync(0xffffffffu, v, o);
    int lane = threadIdx.x & 31, w = threadIdx.x >> 5;
    if (lane == 0) sh[w] = v;
    __syncthreads();
    if (w == 0) {
        v = (lane < 8) ? sh[lane] : 0.f;
        #pragma unroll
        for (int o = 4; o > 0; o >>= 1) v += __shfl_down_sync(0xffffffffu, v, o);
        if (lane == 0) res = v;
    }
    __syncthreads();
    return res;
}

// ---------------- LayerNorm ----------------
__global__ __launch_bounds__(256) void ln_kernel(const float* __restrict__ x,
                                                 const float* __restrict__ w,
                                                 float* __restrict__ out) {
    int row = blockIdx.x;
    const float* xr = x + (size_t)row * D_;
    float* orow = out + (size_t)row * D_;
    float lv[3];
    float s = 0.f;
    #pragma unroll
    for (int i = 0; i < 3; i++) { lv[i] = xr[threadIdx.x + i*256]; s += lv[i]; }
    float mean = block_reduce_sum(s) * (1.f / D_);
    float vs = 0.f;
    #pragma unroll
    for (int i = 0; i < 3; i++) { float d = lv[i] - mean; vs += d * d; }
    float var = block_reduce_sum(vs) * (1.f / D_);
    float rstd = rsqrtf(var + EPS_);
    #pragma unroll
    for (int i = 0; i < 3; i++) {
        int c = threadIdx.x + i*256;
        float y = (lv[i] - mean) * rstd;
        if (w) y *= w[c];
        orow[c] = y;
    }
}

// ---------------- elementwise fusions (float4) ----------------
__global__ void ew_adaln_kernel(const float4* __restrict__ an, const float4* __restrict__ sig,
                                const float4* __restrict__ c2, float4* __restrict__ out, int n4) {
    int i = blockIdx.x * blockDim.x + threadIdx.x;
    if (i < n4) {
        float4 a = an[i], s = sig[i], c = c2[i];
        out[i] = make_float4(fmaf(a.x, s.x, c.x), fmaf(a.y, s.y, c.y),
                             fmaf(a.z, s.z, c.z), fmaf(a.w, s.w, c.w));
    }
}
__global__ void ew_mul_kernel(const float4* __restrict__ a, const float4* __restrict__ b,
                              float4* __restrict__ out, int n4) {
    int i = blockIdx.x * blockDim.x + threadIdx.x;
    if (i < n4) {
        float4 x = a[i], y = b[i];
        out[i] = make_float4(x.x * y.x, x.y * y.y, x.z * y.z, x.w * y.w);
    }
}
__global__ void ew_gate_add_kernel(const float4* __restrict__ base, const float4* __restrict__ g,
                                   const float4* __restrict__ x, float4* __restrict__ out, int n4) {
    int i = blockIdx.x * blockDim.x + threadIdx.x;
    if (i < n4) {
        float4 bb = base[i], gg = g[i], xx = x[i];
        out[i] = make_float4(fmaf(gg.x, xx.x, bb.x), fmaf(gg.y, xx.y, bb.y),
                             fmaf(gg.z, xx.z, bb.z), fmaf(gg.w, xx.w, bb.w));
    }
}
__global__ void ew_swiglu_kernel(const float* __restrict__ sw, const float4* __restrict__ ab,
                                 float4* __restrict__ out, int n4) {
    int i = blockIdx.x * blockDim.x + threadIdx.x;
    if (i < n4) {
        int e = i * 4;
        int row = e / HID_, j = e - row * HID_;
        const float4 u  = *(const float4*)(sw + (size_t)row * (2 * HID_) + j);
        const float4 gt = *(const float4*)(sw + (size_t)row * (2 * HID_) + HID_ + j);
        const float4 a = ab[i];
        float4 r;
        r.x = gt.x / (1.f + __expf(-gt.x)) * u.x * a.x;
        r.y = gt.y / (1.f + __expf(-gt.y)) * u.y * a.y;
        r.z = gt.z / (1.f + __expf(-gt.z)) * u.z * a.z;
        r.w = gt.w / (1.f + __expf(-gt.w)) * u.w * a.w;
        out[i] = r;
    }
}

// ---------------- host orchestration ----------------
static float* sym(const void* s) { void* p = nullptr; cudaGetSymbolAddress(&p, s); return (float*)p; }

static GSlice mk(const float* A, const float* W, const float* bias, float* C,
                 int K, int Wstride, int Cstride, int act) {
    GSlice g; g.A = A; g.W = W; g.bias = bias; g.C = C;
    g.K = K; g.Wstride = Wstride; g.Cstride = Cstride; g.act = act;
    return g;
}
static void run_gemms(int Ndim, int nsl, GSlice a, GSlice b,
                      GSlice c = GSlice(), GSlice d = GSlice()) {
    GPack pk; pk.s[0] = a; pk.s[1] = b; pk.s[2] = c; pk.s[3] = d;
    mma_gemm_kernel<<<dim3(Ndim / 128, M_ / 128, nsl), 256, GEMM_SMEM>>>(pk, Ndim);
}

extern "C" void kernel_launch(void* const* d_in, const int* in_sizes, int n_in,
                              void* d_out, int out_size) {
    const float* a          = (const float*)d_in[0];
    const float* s          = (const float*)d_in[1];
    const float* z          = (const float*)d_in[2];
    const float* ad1_snw    = (const float*)d_in[3];
    const float* ad1_ssw    = (const float*)d_in[4];
    const float* ad1_ssb    = (const float*)d_in[5];
    const float* ad1_sbw    = (const float*)d_in[6];
    const float* q_w        = (const float*)d_in[7];
    const float* q_b        = (const float*)d_in[8];
    const float* k_w        = (const float*)d_in[9];
    const float* v_w        = (const float*)d_in[10];
    const float* g_w        = (const float*)d_in[11];
    const float* o_w        = (const float*)d_in[12];
    const float* outproj_w  = (const float*)d_in[13];
    const float* outproj_b  = (const float*)d_in[14];
    const float* ad2_snw    = (const float*)d_in[15];
    const float* ad2_ssw    = (const float*)d_in[16];
    const float* ad2_ssb    = (const float*)d_in[17];
    const float* ad2_sbw    = (const float*)d_in[18];
    const float* swish_w    = (const float*)d_in[19];
    const float* a2b_w      = (const float*)d_in[20];
    const float* b2a_w      = (const float*)d_in[21];
    const float* op_w       = (const float*)d_in[22];
    const float* op_b       = (const float*)d_in[23];
    float* out = (float*)d_out;

    cudaFuncSetAttribute(mma_gemm_kernel, cudaFuncAttributeMaxDynamicSharedMemorySize, GEMM_SMEM);
    cudaFuncSetAttribute(flash_attn_kernel, cudaFuncAttributeMaxDynamicSharedMemorySize, FA_SMEM);

    float *an = sym(g_an), *sn = sym(g_sn), *c1 = sym(g_c1), *c2 = sym(g_c2);
    float *bm = sym(g_bm), *qb = sym(g_q), *kb = sym(g_k), *vb = sym(g_v);
    float *gt = sym(g_gt), *ob = sym(g_o), *og = sym(g_og), *xw = sym(g_xw);
    float *sg = sym(g_sig), *anew = sym(g_anew), *hb = sym(g_hb);
    float *sw = sym(g_sw), *ab = sym(g_ab), *hid = sym(g_hid);

    const int n4MD = M_ * D_ / 4;
    const int n4MH = M_ * HID_ / 4;
    const int EW = 256;

    // ===== adaLN 1 =====
    ln_kernel<<<M_, 256>>>(a, nullptr, an);
    ln_kernel<<<M_, 256>>>(s, ad1_snw, sn);
    run_gemms(D_, 2,
        mk(sn, ad1_ssw, ad1_ssb, c1, D_, D_, D_, 1),
        mk(sn, ad1_sbw, nullptr, c2, D_, D_, D_, 0));
    ew_adaln_kernel<<<(n4MD + EW - 1) / EW, EW>>>((const float4*)an, (const float4*)c1,
                                                  (const float4*)c2, (float4*)bm, n4MD);

    // ===== QKVG projections (one launch, 384 CTAs) =====
    run_gemms(D_, 4,
        mk(bm, q_w, q_b,     qb, D_, D_, D_, 0),
        mk(bm, k_w, nullptr, kb, D_, D_, D_, 0),
        mk(bm, v_w, nullptr, vb, D_, D_, D_, 0),
        mk(bm, g_w, nullptr, gt, D_, D_, D_, 1));

    // ===== fused flash attention =====
    flash_attn_kernel<<<dim3(N_ / 64, H_ * B_), 128, FA_SMEM>>>(qb, kb, vb, z, ob);

    // ===== output projection + gated residual =====
    ew_mul_kernel<<<(n4MD + EW - 1) / EW, EW>>>((const float4*)ob, (const float4*)gt,
                                                (float4*)og, n4MD);
    run_gemms(D_, 2,
        mk(og, o_w, nullptr, xw, D_, D_, D_, 0),
        mk(s, outproj_w, outproj_b, sg, D_, D_, D_, 1));
    ew_gate_add_kernel<<<(n4MD + EW - 1) / EW, EW>>>((const float4*)a, (const float4*)sg,
                                                     (const float4*)xw, (float4*)anew, n4MD);

    // ===== adaLN 2 =====
    ln_kernel<<<M_, 256>>>(anew, nullptr, an);
    ln_kernel<<<M_, 256>>>(s, ad2_snw, sn);
    run_gemms(D_, 2,
        mk(sn, ad2_ssw, ad2_ssb, c1, D_, D_, D_, 1),
        mk(sn, ad2_sbw, nullptr, c2, D_, D_, D_, 0));
    ew_adaln_kernel<<<(n4MD + EW - 1) / EW, EW>>>((const float4*)an, (const float4*)c1,
                                                  (const float4*)c2, (float4*)bm, n4MD);

    // ===== MLP (swish split into two N=1536 slices + a2b, one launch) =====
    run_gemms(HID_, 3,
        mk(bm, swish_w,        nullptr, sw,        D_, 2*HID_, 2*HID_, 0),
        mk(bm, swish_w + HID_, nullptr, sw + HID_, D_, 2*HID_, 2*HID_, 0),
        mk(bm, a2b_w,          nullptr, ab,        D_, HID_,   HID_,   0));
    ew_swiglu_kernel<<<(n4MH + EW - 1) / EW, EW>>>(sw, (const float4*)ab, (float4*)hid, n4MH);
    run_gemms(D_, 2,
        mk(hid, b2a_w, nullptr, hb, HID_, D_, D_, 0),
        mk(s,   op_w,  op_b,    sg, D_,   D_, D_, 1));
    ew_gate_add_kernel<<<(n4MD + EW - 1) / EW, EW>>>((const float4*)anew, (const float4*)sg,
                                                     (const float4*)hb, (float4*)out, n4MD);
}

// round 6
// speedup vs baseline: 5.8164x; 1.4398x over previous
#include <cuda_runtime.h>
#include <cuda_bf16.h>
#include <math.h>
#include <stdint.h>

#define B_   2
#define N_   1024
#define D_   768
#define H_   16
#define HD_  48
#define HID_ 1536
#define M_   (B_*N_)      // 2048
#define EPS_ 1e-5f

// ---------------- scratch (static device buffers; no allocation) ----------------
__device__ float g_an  [M_*D_];
__device__ float g_sn  [M_*D_];
__device__ float g_c1  [M_*D_];
__device__ float g_c2  [M_*D_];
__device__ float g_bm  [M_*D_];
__device__ float g_q   [M_*D_];
__device__ float g_k   [M_*D_];
__device__ float g_v   [M_*D_];
__device__ float g_gt  [M_*D_];
__device__ float g_o   [M_*D_];
__device__ float g_og  [M_*D_];
__device__ float g_xw  [M_*D_];
__device__ float g_sig [M_*D_];
__device__ float g_anew[M_*D_];
__device__ float g_hb  [M_*D_];
__device__ float g_sw  [M_*2*HID_];
__device__ float g_ab  [M_*HID_];
__device__ float g_hid [M_*HID_];

// =================================================================================
// helpers
// =================================================================================
__device__ __forceinline__ uint32_t smem_u32(const void* p) {
    uint32_t a;
    asm("{ .reg .u64 t; cvta.to.shared.u64 t, %1; cvt.u32.u64 %0, t; }" : "=r"(a) : "l"(p));
    return a;
}
__device__ __forceinline__ uint32_t f2tf32(float f) {
    uint32_t u;
    asm("cvt.rna.tf32.f32 %0, %1;" : "=r"(u) : "f"(f));
    return u;
}
__device__ __forceinline__ void mma_m16n8k8(float* c, const uint32_t* a, const uint32_t* b) {
    asm volatile(
        "mma.sync.aligned.m16n8k8.row.col.f32.tf32.tf32.f32 "
        "{%0,%1,%2,%3}, {%4,%5,%6,%7}, {%8,%9}, {%0,%1,%2,%3};"
        : "+f"(c[0]), "+f"(c[1]), "+f"(c[2]), "+f"(c[3])
        : "r"(a[0]), "r"(a[1]), "r"(a[2]), "r"(a[3]), "r"(b[0]), "r"(b[1]));
}
__device__ __forceinline__ void mma_bf16(float* c, const uint32_t* a, const uint32_t* b) {
    asm volatile(
        "mma.sync.aligned.m16n8k16.row.col.f32.bf16.bf16.f32 "
        "{%0,%1,%2,%3}, {%4,%5,%6,%7}, {%8,%9}, {%0,%1,%2,%3};"
        : "+f"(c[0]), "+f"(c[1]), "+f"(c[2]), "+f"(c[3])
        : "r"(a[0]), "r"(a[1]), "r"(a[2]), "r"(a[3]), "r"(b[0]), "r"(b[1]));
}
__device__ __forceinline__ void ldsm_x4(uint32_t* r, uint32_t addr) {
    asm volatile("ldmatrix.sync.aligned.m8n8.x4.shared.b16 {%0,%1,%2,%3}, [%4];"
        : "=r"(r[0]), "=r"(r[1]), "=r"(r[2]), "=r"(r[3]) : "r"(addr));
}
__device__ __forceinline__ void ldsm_x4_t(uint32_t* r, uint32_t addr) {
    asm volatile("ldmatrix.sync.aligned.m8n8.x4.trans.shared.b16 {%0,%1,%2,%3}, [%4];"
        : "=r"(r[0]), "=r"(r[1]), "=r"(r[2]), "=r"(r[3]) : "r"(addr));
}
__device__ __forceinline__ uint2 f4_to_bf16x4(float4 v) {
    __nv_bfloat162 lo = __float22bfloat162_rn(make_float2(v.x, v.y));
    __nv_bfloat162 hi = __float22bfloat162_rn(make_float2(v.z, v.w));
    uint2 r;
    r.x = *(uint32_t*)&lo;
    r.y = *(uint32_t*)&hi;
    return r;
}

// =================================================================================
// multi-slice bf16 GEMM: per z-slice C[M,N]=A[M,K]@W[K,N] (+bias)(+sigmoid)
// 128x128x32 block tile, 256 thr, 8 warps (2x4), warp tile 64x32, m16n8k16 bf16.
// A rows padded to 80B (16B-aligned for ldmatrix), B rows to 272B.
// =================================================================================
struct GSlice {
    const float* A; const float* W; const float* bias; float* C;
    int K; int Wstride; int Cstride; int act;
};
struct GPack { GSlice s[4]; };

#define A_ROWB 80
#define B_ROWB 272
#define A_STG  (128*A_ROWB)   // 10240 B
#define B_STG  (32*B_ROWB)    // 8704 B
#define GEMM_SMEM (2*(A_STG + B_STG))   // 37888 B

__global__ __launch_bounds__(256, 2) void mma_gemm_kernel(GPack pk, int Ndim)
{
    extern __shared__ char sm[];
    const uint32_t sbA = smem_u32(sm);
    const uint32_t sbB = sbA + 2 * A_STG;

    const GSlice sl = pk.s[blockIdx.z];
    const float* A = sl.A;
    const float* W = sl.W;
    const int Kdim = sl.K, Wstr = sl.Wstride, Cstr = sl.Cstride, act = sl.act;

    const int tid  = threadIdx.x;
    const int lane = tid & 31, wid = tid >> 5;
    const int wm0  = (wid >> 2) * 64;
    const int wn0  = (wid & 3)  * 32;
    const int tq   = lane >> 2, tr = lane & 3;
    const int bm   = blockIdx.y * 128, bn = blockIdx.x * 128;

    const int ar = tid >> 3, ac = (tid & 7) * 4;    // A: 32 rows/pass, 8 f4/row
    const int br = tid >> 5, bc = (tid & 31) * 4;   // B: 8 k-rows/pass, 32 f4/row

    // ldmatrix lane->address components
    const int lm  = lane >> 3;       // matrix id 0..3
    const int li  = lane & 7;        // row in matrix
    const int a_r = (lm & 1) * 8 + li, a_k = (lm >> 1) * 8;   // A tiles: (m-oct, k-oct)
    const int b_k = (lm & 1) * 8 + li, b_n = (lm >> 1) * 8;   // B tiles: (k-oct, n-oct)

    float acc[4][4][4];
    #pragma unroll
    for (int i = 0; i < 4; i++)
        #pragma unroll
        for (int j = 0; j < 4; j++)
            #pragma unroll
            for (int q = 0; q < 4; q++) acc[i][j][q] = 0.f;

    const int KC = Kdim >> 5;
    uint2 abf[4], bbf[4];

    // ---- prologue: load+convert tile 0 ----
    #pragma unroll
    for (int p = 0; p < 4; p++)
        abf[p] = f4_to_bf16x4(*(const float4*)(A + (size_t)(bm + ar + p * 32) * Kdim + ac));
    #pragma unroll
    for (int p = 0; p < 4; p++)
        bbf[p] = f4_to_bf16x4(*(const float4*)(W + (size_t)(br + p * 8) * Wstr + bn + bc));
    #pragma unroll
    for (int p = 0; p < 4; p++)
        *(uint2*)(sm + ((ar + p * 32) * A_ROWB + ac * 2)) = abf[p];
    #pragma unroll
    for (int p = 0; p < 4; p++)
        *(uint2*)(sm + 2 * A_STG + ((br + p * 8) * B_ROWB + bc * 2)) = bbf[p];
    __syncthreads();

    for (int it = 0; it < KC; it++) {
        const int cur = it & 1;
        if (it + 1 < KC) {
            const int k0 = (it + 1) << 5;
            #pragma unroll
            for (int p = 0; p < 4; p++)
                abf[p] = f4_to_bf16x4(*(const float4*)(A + (size_t)(bm + ar + p * 32) * Kdim + k0 + ac));
            #pragma unroll
            for (int p = 0; p < 4; p++)
                bbf[p] = f4_to_bf16x4(*(const float4*)(W + (size_t)(k0 + br + p * 8) * Wstr + bn + bc));
        }
        const uint32_t Ab = sbA + cur * A_STG;
        const uint32_t Bb = sbB + cur * B_STG;
        #pragma unroll
        for (int ks = 0; ks < 2; ks++) {
            uint32_t af[4][4], bf[2][4];
            #pragma unroll
            for (int mf = 0; mf < 4; mf++)
                ldsm_x4(af[mf], Ab + (wm0 + mf * 16 + a_r) * A_ROWB + (ks * 16 + a_k) * 2);
            #pragma unroll
            for (int np = 0; np < 2; np++)
                ldsm_x4_t(bf[np], Bb + (ks * 16 + b_k) * B_ROWB + (wn0 + np * 16 + b_n) * 2);
            #pragma unroll
            for (int mf = 0; mf < 4; mf++) {
                #pragma unroll
                for (int nf = 0; nf < 4; nf++)
                    mma_bf16(acc[mf][nf], af[mf], bf[nf >> 1] + (nf & 1) * 2);
            }
        }
        if (it + 1 < KC) {
            const int nxt = (it + 1) & 1;
            #pragma unroll
            for (int p = 0; p < 4; p++)
                *(uint2*)(sm + nxt * A_STG + ((ar + p * 32) * A_ROWB + ac * 2)) = abf[p];
            #pragma unroll
            for (int p = 0; p < 4; p++)
                *(uint2*)(sm + 2 * A_STG + nxt * B_STG + ((br + p * 8) * B_ROWB + bc * 2)) = bbf[p];
            __syncthreads();
        }
    }

    // ---- epilogue ----
    #pragma unroll
    for (int mf = 0; mf < 4; mf++) {
        const int row = bm + wm0 + mf * 16 + tq;
        #pragma unroll
        for (int nf = 0; nf < 4; nf++) {
            const int col = bn + wn0 + nf * 8 + 2 * tr;
            float b0 = 0.f, b1 = 0.f;
            if (sl.bias) { b0 = sl.bias[col]; b1 = sl.bias[col + 1]; }
            float v0 = acc[mf][nf][0] + b0;
            float v1 = acc[mf][nf][1] + b1;
            float v2 = acc[mf][nf][2] + b0;
            float v3 = acc[mf][nf][3] + b1;
            if (act == 1) {
                v0 = 1.f / (1.f + __expf(-v0));
                v1 = 1.f / (1.f + __expf(-v1));
                v2 = 1.f / (1.f + __expf(-v2));
                v3 = 1.f / (1.f + __expf(-v3));
            }
            *(float2*)(sl.C + (size_t)row * Cstr + col)       = make_float2(v0, v1);
            *(float2*)(sl.C + (size_t)(row + 8) * Cstr + col) = make_float2(v2, v3);
        }
    }
}

// =================================================================================
// flash attention, tf32 mma. One CTA = 64 q-rows of one (h,b). 4 warps, 128 thr.
// =================================================================================
#define QSTR 52
#define PSTR 68
#define FA_Q  0
#define FA_K  3328
#define FA_V  6656
#define FA_P  9984
#define FA_SMEM ((9984 + 64*PSTR)*4)   // 57344 bytes

__global__ __launch_bounds__(128) void flash_attn_kernel(
    const float* __restrict__ q, const float* __restrict__ k,
    const float* __restrict__ v, const float* __restrict__ z,
    float* __restrict__ o)
{
    extern __shared__ float fsm[];
    float* Qs = fsm + FA_Q;
    float* Ks = fsm + FA_K;
    float* Vs = fsm + FA_V;
    float* Ps = fsm + FA_P;

    const int tid = threadIdx.x, lane = tid & 31, wq = tid >> 5;
    const int tq = lane >> 2, tr = lane & 3;
    const int qt = blockIdx.x;
    const int hb = blockIdx.y;
    const int h = hb / B_, b = hb % B_;
    const int q0 = qt * 64;
    const float scale = 0.14433756729740643f;

    for (int e = tid; e < 64 * 12; e += 128) {
        const int r = e / 12, c4 = (e % 12) * 4;
        const float4 vq = *(const float4*)(q + ((size_t)(b * N_) + q0 + r) * D_ + h * HD_ + c4);
        uint4 u;
        u.x = f2tf32(vq.x); u.y = f2tf32(vq.y); u.z = f2tf32(vq.z); u.w = f2tf32(vq.w);
        *(uint4*)(Qs + r * QSTR + c4) = u;
    }
    __syncthreads();

    const int rowa = wq * 16 + tq;
    uint32_t qf[6][4];
    #pragma unroll
    for (int kk = 0; kk < 6; kk++) {
        qf[kk][0] = __float_as_uint(Qs[rowa * QSTR + kk * 8 + tr]);
        qf[kk][1] = __float_as_uint(Qs[(rowa + 8) * QSTR + kk * 8 + tr]);
        qf[kk][2] = __float_as_uint(Qs[rowa * QSTR + kk * 8 + tr + 4]);
        qf[kk][3] = __float_as_uint(Qs[(rowa + 8) * QSTR + kk * 8 + tr + 4]);
    }

    float m0 = -1e30f, m1 = -1e30f, l0 = 0.f, l1 = 0.f;
    float O[6][4];
    #pragma unroll
    for (int i = 0; i < 6; i++)
        #pragma unroll
        for (int j = 0; j < 4; j++) O[i][j] = 0.f;

    for (int t = 0; t < 16; t++) {
        __syncthreads();
        for (int e = tid; e < 64 * 12; e += 128) {
            const int r = e / 12, c4 = (e % 12) * 4;
            const size_t gof = ((size_t)(b * N_) + t * 64 + r) * D_ + h * HD_ + c4;
            const float4 vk = *(const float4*)(k + gof);
            const float4 vv = *(const float4*)(v + gof);
            uint4 uk, uv;
            uk.x = f2tf32(vk.x); uk.y = f2tf32(vk.y); uk.z = f2tf32(vk.z); uk.w = f2tf32(vk.w);
            uv.x = f2tf32(vv.x); uv.y = f2tf32(vv.y); uv.z = f2tf32(vv.z); uv.w = f2tf32(vv.w);
            *(uint4*)(Ks + r * QSTR + c4) = uk;
            *(uint4*)(Vs + r * QSTR + c4) = uv;
        }
        __syncthreads();

        float c[8][4];
        #pragma unroll
        for (int nf = 0; nf < 8; nf++)
            #pragma unroll
            for (int j = 0; j < 4; j++) c[nf][j] = 0.f;
        #pragma unroll
        for (int nf = 0; nf < 8; nf++) {
            #pragma unroll
            for (int kk = 0; kk < 6; kk++) {
                uint32_t bfv[2];
                bfv[0] = __float_as_uint(Ks[(nf * 8 + tq) * QSTR + kk * 8 + tr]);
                bfv[1] = __float_as_uint(Ks[(nf * 8 + tq) * QSTR + kk * 8 + tr + 4]);
                mma_m16n8k8(c[nf], qf[kk], bfv);
            }
        }

        float mx0 = -1e30f, mx1 = -1e30f;
        const size_t zb0 = (((size_t)hb) * N_ + q0 + rowa) * N_ + t * 64 + 2 * tr;
        #pragma unroll
        for (int nf = 0; nf < 8; nf++) {
            const float2 z0 = *(const float2*)(z + zb0 + nf * 8);
            const float2 z1 = *(const float2*)(z + zb0 + (size_t)8 * N_ + nf * 8);
            c[nf][0] = fmaf(c[nf][0], scale, z0.x);
            c[nf][1] = fmaf(c[nf][1], scale, z0.y);
            c[nf][2] = fmaf(c[nf][2], scale, z1.x);
            c[nf][3] = fmaf(c[nf][3], scale, z1.y);
            mx0 = fmaxf(mx0, fmaxf(c[nf][0], c[nf][1]));
            mx1 = fmaxf(mx1, fmaxf(c[nf][2], c[nf][3]));
        }
        mx0 = fmaxf(mx0, __shfl_xor_sync(0xffffffffu, mx0, 1));
        mx0 = fmaxf(mx0, __shfl_xor_sync(0xffffffffu, mx0, 2));
        mx1 = fmaxf(mx1, __shfl_xor_sync(0xffffffffu, mx1, 1));
        mx1 = fmaxf(mx1, __shfl_xor_sync(0xffffffffu, mx1, 2));
        const float mn0 = fmaxf(m0, mx0), mn1 = fmaxf(m1, mx1);
        const float a0 = __expf(m0 - mn0), a1 = __expf(m1 - mn1);

        float rs0 = 0.f, rs1 = 0.f;
        #pragma unroll
        for (int nf = 0; nf < 8; nf++) {
            const float p0 = __expf(c[nf][0] - mn0);
            const float p1 = __expf(c[nf][1] - mn0);
            const float p2 = __expf(c[nf][2] - mn1);
            const float p3 = __expf(c[nf][3] - mn1);
            rs0 += p0 + p1; rs1 += p2 + p3;
            uint2 u0, u1;
            u0.x = f2tf32(p0); u0.y = f2tf32(p1);
            u1.x = f2tf32(p2); u1.y = f2tf32(p3);
            *(uint2*)(Ps + rowa * PSTR + nf * 8 + 2 * tr)       = u0;
            *(uint2*)(Ps + (rowa + 8) * PSTR + nf * 8 + 2 * tr) = u1;
        }
        rs0 += __shfl_xor_sync(0xffffffffu, rs0, 1);
        rs0 += __shfl_xor_sync(0xffffffffu, rs0, 2);
        rs1 += __shfl_xor_sync(0xffffffffu, rs1, 1);
        rs1 += __shfl_xor_sync(0xffffffffu, rs1, 2);
        l0 = l0 * a0 + rs0;
        l1 = l1 * a1 + rs1;
        m0 = mn0; m1 = mn1;

        #pragma unroll
        for (int nf = 0; nf < 6; nf++) {
            O[nf][0] *= a0; O[nf][1] *= a0;
            O[nf][2] *= a1; O[nf][3] *= a1;
        }
        __syncwarp();

        #pragma unroll
        for (int ks = 0; ks < 8; ks++) {
            uint32_t pf[4];
            pf[0] = __float_as_uint(Ps[rowa * PSTR + ks * 8 + tr]);
            pf[1] = __float_as_uint(Ps[(rowa + 8) * PSTR + ks * 8 + tr]);
            pf[2] = __float_as_uint(Ps[rowa * PSTR + ks * 8 + tr + 4]);
            pf[3] = __float_as_uint(Ps[(rowa + 8) * PSTR + ks * 8 + tr + 4]);
            #pragma unroll
            for (int nf = 0; nf < 6; nf++) {
                uint32_t vf[2];
                vf[0] = __float_as_uint(Vs[(ks * 8 + tr) * QSTR + nf * 8 + tq]);
                vf[1] = __float_as_uint(Vs[(ks * 8 + tr + 4) * QSTR + nf * 8 + tq]);
                mma_m16n8k8(O[nf], pf, vf);
            }
        }
    }

    const float il0 = 1.f / l0, il1 = 1.f / l1;
    const size_t ob0 = ((size_t)(b * N_) + q0 + rowa) * D_ + h * HD_ + 2 * tr;
    #pragma unroll
    for (int nf = 0; nf < 6; nf++) {
        *(float2*)(o + ob0 + nf * 8)                  = make_float2(O[nf][0] * il0, O[nf][1] * il0);
        *(float2*)(o + ob0 + (size_t)8 * D_ + nf * 8) = make_float2(O[nf][2] * il1, O[nf][3] * il1);
    }
}

// ---------------- block reduction ----------------
__device__ __forceinline__ float block_reduce_sum(float v) {
    __shared__ float sh[8];
    __shared__ float res;
    __syncthreads();
    #pragma unroll
    for (int o = 16; o > 0; o >>= 1) v += __shfl_down_sync(0xffffffffu, v, o);
    int lane = threadIdx.x & 31, w = threadIdx.x >> 5;
    if (lane == 0) sh[w] = v;
    __syncthreads();
    if (w == 0) {
        v = (lane < 8) ? sh[lane] : 0.f;
        #pragma unroll
        for (int o = 4; o > 0; o >>= 1) v += __shfl_down_sync(0xffffffffu, v, o);
        if (lane == 0) res = v;
    }
    __syncthreads();
    return res;
}

// ---------------- LayerNorm ----------------
__global__ __launch_bounds__(256) void ln_kernel(const float* __restrict__ x,
                                                 const float* __restrict__ w,
                                                 float* __restrict__ out) {
    int row = blockIdx.x;
    const float* xr = x + (size_t)row * D_;
    float* orow = out + (size_t)row * D_;
    float lv[3];
    float s = 0.f;
    #pragma unroll
    for (int i = 0; i < 3; i++) { lv[i] = xr[threadIdx.x + i*256]; s += lv[i]; }
    float mean = block_reduce_sum(s) * (1.f / D_);
    float vs = 0.f;
    #pragma unroll
    for (int i = 0; i < 3; i++) { float d = lv[i] - mean; vs += d * d; }
    float var = block_reduce_sum(vs) * (1.f / D_);
    float rstd = rsqrtf(var + EPS_);
    #pragma unroll
    for (int i = 0; i < 3; i++) {
        int c = threadIdx.x + i*256;
        float y = (lv[i] - mean) * rstd;
        if (w) y *= w[c];
        orow[c] = y;
    }
}

// ---------------- elementwise fusions (float4) ----------------
__global__ void ew_adaln_kernel(const float4* __restrict__ an, const float4* __restrict__ sig,
                                const float4* __restrict__ c2, float4* __restrict__ out, int n4) {
    int i = blockIdx.x * blockDim.x + threadIdx.x;
    if (i < n4) {
        float4 a = an[i], s = sig[i], c = c2[i];
        out[i] = make_float4(fmaf(a.x, s.x, c.x), fmaf(a.y, s.y, c.y),
                             fmaf(a.z, s.z, c.z), fmaf(a.w, s.w, c.w));
    }
}
__global__ void ew_mul_kernel(const float4* __restrict__ a, const float4* __restrict__ b,
                              float4* __restrict__ out, int n4) {
    int i = blockIdx.x * blockDim.x + threadIdx.x;
    if (i < n4) {
        float4 x = a[i], y = b[i];
        out[i] = make_float4(x.x * y.x, x.y * y.y, x.z * y.z, x.w * y.w);
    }
}
__global__ void ew_gate_add_kernel(const float4* __restrict__ base, const float4* __restrict__ g,
                                   const float4* __restrict__ x, float4* __restrict__ out, int n4) {
    int i = blockIdx.x * blockDim.x + threadIdx.x;
    if (i < n4) {
        float4 bb = base[i], gg = g[i], xx = x[i];
        out[i] = make_float4(fmaf(gg.x, xx.x, bb.x), fmaf(gg.y, xx.y, bb.y),
                             fmaf(gg.z, xx.z, bb.z), fmaf(gg.w, xx.w, bb.w));
    }
}
__global__ void ew_swiglu_kernel(const float* __restrict__ sw, const float4* __restrict__ ab,
                                 float4* __restrict__ out, int n4) {
    int i = blockIdx.x * blockDim.x + threadIdx.x;
    if (i < n4) {
        int e = i * 4;
        int row = e / HID_, j = e - row * HID_;
        const float4 u  = *(const float4*)(sw + (size_t)row * (2 * HID_) + j);
        const float4 gt = *(const float4*)(sw + (size_t)row * (2 * HID_) + HID_ + j);
        const float4 a = ab[i];
        float4 r;
        r.x = gt.x / (1.f + __expf(-gt.x)) * u.x * a.x;
        r.y = gt.y / (1.f + __expf(-gt.y)) * u.y * a.y;
        r.z = gt.z / (1.f + __expf(-gt.z)) * u.z * a.z;
        r.w = gt.w / (1.f + __expf(-gt.w)) * u.w * a.w;
        out[i] = r;
    }
}

// ---------------- host orchestration ----------------
static float* sym(const void* s) { void* p = nullptr; cudaGetSymbolAddress(&p, s); return (float*)p; }

static GSlice mk(const float* A, const float* W, const float* bias, float* C,
                 int K, int Wstride, int Cstride, int act) {
    GSlice g; g.A = A; g.W = W; g.bias = bias; g.C = C;
    g.K = K; g.Wstride = Wstride; g.Cstride = Cstride; g.act = act;
    return g;
}
static void run_gemms(int Ndim, int nsl, GSlice a, GSlice b,
                      GSlice c = GSlice(), GSlice d = GSlice()) {
    GPack pk; pk.s[0] = a; pk.s[1] = b; pk.s[2] = c; pk.s[3] = d;
    mma_gemm_kernel<<<dim3(Ndim / 128, M_ / 128, nsl), 256, GEMM_SMEM>>>(pk, Ndim);
}

extern "C" void kernel_launch(void* const* d_in, const int* in_sizes, int n_in,
                              void* d_out, int out_size) {
    const float* a          = (const float*)d_in[0];
    const float* s          = (const float*)d_in[1];
    const float* z          = (const float*)d_in[2];
    const float* ad1_snw    = (const float*)d_in[3];
    const float* ad1_ssw    = (const float*)d_in[4];
    const float* ad1_ssb    = (const float*)d_in[5];
    const float* ad1_sbw    = (const float*)d_in[6];
    const float* q_w        = (const float*)d_in[7];
    const float* q_b        = (const float*)d_in[8];
    const float* k_w        = (const float*)d_in[9];
    const float* v_w        = (const float*)d_in[10];
    const float* g_w        = (const float*)d_in[11];
    const float* o_w        = (const float*)d_in[12];
    const float* outproj_w  = (const float*)d_in[13];
    const float* outproj_b  = (const float*)d_in[14];
    const float* ad2_snw    = (const float*)d_in[15];
    const float* ad2_ssw    = (const float*)d_in[16];
    const float* ad2_ssb    = (const float*)d_in[17];
    const float* ad2_sbw    = (const float*)d_in[18];
    const float* swish_w    = (const float*)d_in[19];
    const float* a2b_w      = (const float*)d_in[20];
    const float* b2a_w      = (const float*)d_in[21];
    const float* op_w       = (const float*)d_in[22];
    const float* op_b       = (const float*)d_in[23];
    float* out = (float*)d_out;

    cudaFuncSetAttribute(mma_gemm_kernel, cudaFuncAttributeMaxDynamicSharedMemorySize, GEMM_SMEM);
    cudaFuncSetAttribute(flash_attn_kernel, cudaFuncAttributeMaxDynamicSharedMemorySize, FA_SMEM);

    float *an = sym(g_an), *sn = sym(g_sn), *c1 = sym(g_c1), *c2 = sym(g_c2);
    float *bm = sym(g_bm), *qb = sym(g_q), *kb = sym(g_k), *vb = sym(g_v);
    float *gt = sym(g_gt), *ob = sym(g_o), *og = sym(g_og), *xw = sym(g_xw);
    float *sg = sym(g_sig), *anew = sym(g_anew), *hb = sym(g_hb);
    float *sw = sym(g_sw), *ab = sym(g_ab), *hid = sym(g_hid);

    const int n4MD = M_ * D_ / 4;
    const int n4MH = M_ * HID_ / 4;
    const int EW = 256;

    // ===== adaLN 1 =====
    ln_kernel<<<M_, 256>>>(a, nullptr, an);
    ln_kernel<<<M_, 256>>>(s, ad1_snw, sn);
    run_gemms(D_, 2,
        mk(sn, ad1_ssw, ad1_ssb, c1, D_, D_, D_, 1),
        mk(sn, ad1_sbw, nullptr, c2, D_, D_, D_, 0));
    ew_adaln_kernel<<<(n4MD + EW - 1) / EW, EW>>>((const float4*)an, (const float4*)c1,
                                                  (const float4*)c2, (float4*)bm, n4MD);

    // ===== QKVG projections =====
    run_gemms(D_, 4,
        mk(bm, q_w, q_b,     qb, D_, D_, D_, 0),
        mk(bm, k_w, nullptr, kb, D_, D_, D_, 0),
        mk(bm, v_w, nullptr, vb, D_, D_, D_, 0),
        mk(bm, g_w, nullptr, gt, D_, D_, D_, 1));

    // ===== fused flash attention =====
    flash_attn_kernel<<<dim3(N_ / 64, H_ * B_), 128, FA_SMEM>>>(qb, kb, vb, z, ob);

    // ===== output projection + gated residual =====
    ew_mul_kernel<<<(n4MD + EW - 1) / EW, EW>>>((const float4*)ob, (const float4*)gt,
                                                (float4*)og, n4MD);
    run_gemms(D_, 2,
        mk(og, o_w, nullptr, xw, D_, D_, D_, 0),
        mk(s, outproj_w, outproj_b, sg, D_, D_, D_, 1));
    ew_gate_add_kernel<<<(n4MD + EW - 1) / EW, EW>>>((const float4*)a, (const float4*)sg,
                                                     (const float4*)xw, (float4*)anew, n4MD);

    // ===== adaLN 2 =====
    ln_kernel<<<M_, 256>>>(anew, nullptr, an);
    ln_kernel<<<M_, 256>>>(s, ad2_snw, sn);
    run_gemms(D_, 2,
        mk(sn, ad2_ssw, ad2_ssb, c1, D_, D_, D_, 1),
        mk(sn, ad2_sbw, nullptr, c2, D_, D_, D_, 0));
    ew_adaln_kernel<<<(n4MD + EW - 1) / EW, EW>>>((const float4*)an, (const float4*)c1,
                                                  (const float4*)c2, (float4*)bm, n4MD);

    // ===== MLP =====
    run_gemms(HID_, 3,
        mk(bm, swish_w,        nullptr, sw,        D_, 2*HID_, 2*HID_, 0),
        mk(bm, swish_w + HID_, nullptr, sw + HID_, D_, 2*HID_, 2*HID_, 0),
        mk(bm, a2b_w,          nullptr, ab,        D_, HID_,   HID_,   0));
    ew_swiglu_kernel<<<(n4MH + EW - 1) / EW, EW>>>(sw, (const float4*)ab, (float4*)hid, n4MH);
    run_gemms(D_, 2,
        mk(hid, b2a_w, nullptr, hb, HID_, D_, D_, 0),
        mk(s,   op_w,  op_b,    sg, D_,   D_, D_, 1));
    ew_gate_add_kernel<<<(n4MD + EW - 1) / EW, EW>>>((const float4*)anew, (const float4*)sg,
                                                     (const float4*)hb, (float4*)out, n4MD);
}